// round 6
// baseline (speedup 1.0000x reference)
#include <cuda_runtime.h>
#include <cuda_fp16.h>
#include <cuda_bf16.h>
#include <math.h>

#define NN 50000
#define MAXE 1600000
#define H 128
#define CC 40
#define EPS 1e-5f

// ---------------- static device scratch ----------------
__device__ __half g_hw[NN * H];      // GEMM output in fp16 (gather source)
__device__ float g_agg[NN * H];      // aggregation output (fp32)
__device__ float g_dis[NN];
__device__ int   g_cnt[NN];
__device__ int   g_rowptr[NN + 1];
__device__ int   g_cursor[NN];
__device__ int   g_csrc[MAXE];
__device__ float g_cw[MAXE];
__device__ int   g_bsum[128];
__device__ int   g_boff[128];
__device__ float g_sum[H];
__device__ float g_sumsq[H];
__device__ float g_scale[H];
__device__ float g_shift[H];
__device__ __nv_bfloat16 g_wthi[H * H];
__device__ __nv_bfloat16 g_wtlo[H * H];
__device__ float g_logits_scratch[NN * CC];

// ---------------- CSR build ----------------
__global__ void k_zero_cnt(int* __restrict__ cnt, int n) {
    int i = blockIdx.x * blockDim.x + threadIdx.x;
    if (i < n) cnt[i] = 0;
}

__global__ void k_count(const int* __restrict__ dst, int* __restrict__ cnt, int e) {
    int i = blockIdx.x * blockDim.x + threadIdx.x;
    if (i < e) atomicAdd(&cnt[dst[i]], 1);
}

// scan pass 1 + dis computation fused
__global__ __launch_bounds__(1024)
void k_scan_blk(const int* __restrict__ cnt, int* __restrict__ rowptr,
                int* __restrict__ bsum, float* __restrict__ dis, int n) {
    __shared__ int warpsums[32];
    int tid = threadIdx.x;
    int lane = tid & 31, wid = tid >> 5;
    int i = blockIdx.x * 1024 + tid;
    int v = (i < n) ? cnt[i] : 0;
    if (i < n) dis[i] = rsqrtf((float)(v + 1));
    int x = v;
#pragma unroll
    for (int o = 1; o < 32; o <<= 1) {
        int t = __shfl_up_sync(0xffffffffu, x, o);
        if (lane >= o) x += t;
    }
    if (lane == 31) warpsums[wid] = x;
    __syncthreads();
    if (wid == 0) {
        int w = warpsums[lane];
#pragma unroll
        for (int o = 1; o < 32; o <<= 1) {
            int t = __shfl_up_sync(0xffffffffu, w, o);
            if (lane >= o) w += t;
        }
        warpsums[lane] = w;
    }
    __syncthreads();
    int excl = x - v + (wid > 0 ? warpsums[wid - 1] : 0);
    if (i < n) rowptr[i] = excl;
    if (tid == 1023) bsum[blockIdx.x] = excl + v;
}

__global__ void k_scan_top(const int* __restrict__ bsum, int* __restrict__ boff, int nb) {
    if (threadIdx.x == 0) {
        int run = 0;
        for (int b = 0; b < nb; b++) { boff[b] = run; run += bsum[b]; }
    }
}

__global__ void k_scan_add(int* __restrict__ rowptr, int* __restrict__ cursor,
                           const int* __restrict__ boff, int n, int e) {
    int i = blockIdx.x * blockDim.x + threadIdx.x;
    if (i < n) {
        int v = rowptr[i] + boff[i >> 10];
        rowptr[i] = v;
        cursor[i] = v;
    }
    if (i == 0) rowptr[n] = e;
}

__global__ void k_fill(const int* __restrict__ src, const int* __restrict__ dst,
                       const float* __restrict__ dis, int* __restrict__ cursor,
                       int* __restrict__ csrc, float* __restrict__ cw, int e) {
    int i = blockIdx.x * blockDim.x + threadIdx.x;
    if (i >= e) return;
    int s = src[i], d = dst[i];
    int pos = atomicAdd(&cursor[d], 1);
    csrc[pos] = s;
    cw[pos] = __ldg(&dis[s]) * __ldg(&dis[d]);
}

// ---------------- W split + BN-stat zeroing (fused) ----------------
__global__ void k_wsplit(const float* __restrict__ W, __nv_bfloat16* __restrict__ wth,
                         __nv_bfloat16* __restrict__ wtl,
                         float* __restrict__ sum, float* __restrict__ sumsq) {
    int i = blockIdx.x * blockDim.x + threadIdx.x;
    if (blockIdx.x == 0 && threadIdx.x < H) { sum[threadIdx.x] = 0.0f; sumsq[threadIdx.x] = 0.0f; }
    if (i >= H * H) return;
    int k = i >> 7, nn = i & 127;
    float v = W[i];
    __nv_bfloat16 h = __float2bfloat16(v);
    float rem = v - __bfloat162float(h);
    wth[nn * H + k] = h;
    wtl[nn * H + k] = __float2bfloat16(rem);
}

// ---------------- GEMM via bf16 split MMA ----------------
__device__ __forceinline__ void mma16816(float* c, const unsigned* a, const unsigned* b) {
    asm volatile(
        "mma.sync.aligned.m16n8k16.row.col.f32.bf16.bf16.f32 "
        "{%0,%1,%2,%3}, {%4,%5,%6,%7}, {%8,%9}, {%0,%1,%2,%3};"
        : "+f"(c[0]), "+f"(c[1]), "+f"(c[2]), "+f"(c[3])
        : "r"(a[0]), "r"(a[1]), "r"(a[2]), "r"(a[3]), "r"(b[0]), "r"(b[1]));
}

#define APITCH 40

__global__ __launch_bounds__(256, 2)
void k_gemm_mma(const float* __restrict__ A,
                const unsigned* __restrict__ wth,
                const unsigned* __restrict__ wtl,
                const float* __restrict__ scale, const float* __restrict__ shift,
                __half* __restrict__ Cout, int n) {
    __shared__ __nv_bfloat16 As_hi[128 * APITCH];
    __shared__ __nv_bfloat16 As_lo[128 * APITCH];
    __shared__ __nv_bfloat16 Ws_hi[128 * APITCH];
    __shared__ __nv_bfloat16 Ws_lo[128 * APITCH];

    int tid = threadIdx.x;
    int w = tid >> 5, lane = tid & 31;
    int wm = w >> 2, wn = w & 3;
    int g = lane >> 2, tig = lane & 3;
    int row0blk = blockIdx.x * 128;

    float acc[4][4][4];
#pragma unroll
    for (int a = 0; a < 4; a++)
#pragma unroll
        for (int b = 0; b < 4; b++)
#pragma unroll
            for (int c = 0; c < 4; c++) acc[a][b][c] = 0.0f;

    for (int k0 = 0; k0 < 128; k0 += 32) {
        for (int i = tid; i < 128 * 32; i += 256) {
            int r = i >> 5, c = i & 31;
            int gr = row0blk + r;
            float v = 0.0f;
            if (gr < n) {
                v = A[(size_t)gr * 128 + k0 + c];
                if (scale) v = fmaxf(v * scale[k0 + c] + shift[k0 + c], 0.0f);
            }
            __nv_bfloat16 h = __float2bfloat16(v);
            As_hi[r * APITCH + c] = h;
            As_lo[r * APITCH + c] = __float2bfloat16(v - __bfloat162float(h));
        }
        for (int i = tid; i < 2048; i += 256) {
            int nn = i >> 4, kk = i & 15;
            ((unsigned*)&Ws_hi[nn * APITCH])[kk] = wth[nn * 64 + (k0 >> 1) + kk];
            ((unsigned*)&Ws_lo[nn * APITCH])[kk] = wtl[nn * 64 + (k0 >> 1) + kk];
        }
        __syncthreads();

#pragma unroll
        for (int ks = 0; ks < 2; ks++) {
            int ca = ks * 16 + 2 * tig;
            unsigned ah[4][4], al[4][4];
#pragma unroll
            for (int mf = 0; mf < 4; mf++) {
                int r0 = (wm * 64 + mf * 16 + g) * APITCH;
                int r1 = r0 + 8 * APITCH;
                ah[mf][0] = *(const unsigned*)&As_hi[r0 + ca];
                ah[mf][1] = *(const unsigned*)&As_hi[r1 + ca];
                ah[mf][2] = *(const unsigned*)&As_hi[r0 + ca + 8];
                ah[mf][3] = *(const unsigned*)&As_hi[r1 + ca + 8];
                al[mf][0] = *(const unsigned*)&As_lo[r0 + ca];
                al[mf][1] = *(const unsigned*)&As_lo[r1 + ca];
                al[mf][2] = *(const unsigned*)&As_lo[r0 + ca + 8];
                al[mf][3] = *(const unsigned*)&As_lo[r1 + ca + 8];
            }
#pragma unroll
            for (int nf = 0; nf < 4; nf++) {
                int nb = (wn * 32 + nf * 8 + g) * APITCH;
                unsigned bh[2], bl[2];
                bh[0] = *(const unsigned*)&Ws_hi[nb + ca];
                bh[1] = *(const unsigned*)&Ws_hi[nb + ca + 8];
                bl[0] = *(const unsigned*)&Ws_lo[nb + ca];
                bl[1] = *(const unsigned*)&Ws_lo[nb + ca + 8];
#pragma unroll
                for (int mf = 0; mf < 4; mf++) {
                    mma16816(acc[mf][nf], ah[mf], bh);
                    mma16816(acc[mf][nf], ah[mf], bl);
                    mma16816(acc[mf][nf], al[mf], bh);
                }
            }
        }
        __syncthreads();
    }

#pragma unroll
    for (int mf = 0; mf < 4; mf++) {
        int gr0 = row0blk + wm * 64 + mf * 16 + g;
        int gr1 = gr0 + 8;
#pragma unroll
        for (int nf = 0; nf < 4; nf++) {
            int col = wn * 32 + nf * 8 + 2 * tig;
            if (gr0 < n) {
                __half2 h = __floats2half2_rn(acc[mf][nf][0], acc[mf][nf][1]);
                *(unsigned*)&Cout[(size_t)gr0 * 128 + col] = *(unsigned*)&h;
            }
            if (gr1 < n) {
                __half2 h = __floats2half2_rn(acc[mf][nf][2], acc[mf][nf][3]);
                *(unsigned*)&Cout[(size_t)gr1 * 128 + col] = *(unsigned*)&h;
            }
        }
    }
}

// ---------------- pull aggregation: vectorized index loads + prefetch pipeline ----------------
__device__ __forceinline__ void acc_row(float4& acc, const uint2& a, float w) {
    float2 p = __half22float2(*(__half2*)&a.x);
    float2 q = __half22float2(*(__half2*)&a.y);
    acc.x += w * p.x; acc.y += w * p.y; acc.z += w * q.x; acc.w += w * q.y;
}

__global__ __launch_bounds__(256)
void k_aggregate(const __half* __restrict__ hw, const int* __restrict__ rowptr,
                 const int* __restrict__ csrc, const float* __restrict__ cw,
                 const float* __restrict__ bias, const float* __restrict__ dis,
                 float* __restrict__ agg, float* __restrict__ bsum,
                 float* __restrict__ bsumsq, int n) {
    __shared__ float ssum[128];
    __shared__ float ssq[128];
    int tid = threadIdx.x;
    if (tid < 128) { ssum[tid] = 0.0f; ssq[tid] = 0.0f; }
    __syncthreads();

    int warp = tid >> 5, lane = tid & 31;
    int node = blockIdx.x * 8 + warp;
    if (node < n) {
        const uint2* hw2 = (const uint2*)hw;
        float d = dis[node];
        float sn = d * d;
        float4 b = ((const float4*)bias)[lane];

        uint2 u0 = __ldg(&hw2[(size_t)node * 32 + lane]);
        float2 f0 = __half22float2(*(__half2*)&u0.x);
        float2 f1 = __half22float2(*(__half2*)&u0.y);
        float4 acc;
        acc.x = b.x + sn * f0.x;
        acc.y = b.y + sn * f0.y;
        acc.z = b.z + sn * f1.x;
        acc.w = b.w + sn * f1.y;

        int j = rowptr[node];
        int end = rowptr[node + 1];

        // scalar peel to 4-alignment
        while (j < end && (j & 3)) {
            int i0 = __ldg(&csrc[j]);
            float w0 = __ldg(&cw[j]);
            uint2 a0 = __ldg(&hw2[(size_t)i0 * 32 + lane]);
            acc_row(acc, a0, w0);
            j++;
        }

        int nvec = (end - j) >> 2;
        if (nvec > 0) {
            const int4* cs4 = (const int4*)(csrc + j);
            const float4* cw4 = (const float4*)(cw + j);
            int4 idx = __ldg(cs4);
            float4 wv = __ldg(cw4);
            for (int gidx = 0; gidx < nvec; gidx++) {
                int4 idx_n; float4 wv_n;
                if (gidx + 1 < nvec) {
                    idx_n = __ldg(cs4 + gidx + 1);
                    wv_n  = __ldg(cw4 + gidx + 1);
                }
                uint2 a0 = __ldg(&hw2[(size_t)idx.x * 32 + lane]);
                uint2 a1 = __ldg(&hw2[(size_t)idx.y * 32 + lane]);
                uint2 a2 = __ldg(&hw2[(size_t)idx.z * 32 + lane]);
                uint2 a3 = __ldg(&hw2[(size_t)idx.w * 32 + lane]);
                acc_row(acc, a0, wv.x);
                acc_row(acc, a1, wv.y);
                acc_row(acc, a2, wv.z);
                acc_row(acc, a3, wv.w);
                idx = idx_n; wv = wv_n;
            }
            j += nvec << 2;
        }
        // tail
        for (; j < end; j++) {
            int i0 = __ldg(&csrc[j]);
            float w0 = __ldg(&cw[j]);
            uint2 a0 = __ldg(&hw2[(size_t)i0 * 32 + lane]);
            acc_row(acc, a0, w0);
        }

        ((float4*)agg)[(size_t)node * 32 + lane] = acc;

        int c = lane * 4;
        atomicAdd(&ssum[c + 0], acc.x); atomicAdd(&ssq[c + 0], acc.x * acc.x);
        atomicAdd(&ssum[c + 1], acc.y); atomicAdd(&ssq[c + 1], acc.y * acc.y);
        atomicAdd(&ssum[c + 2], acc.z); atomicAdd(&ssq[c + 2], acc.z * acc.z);
        atomicAdd(&ssum[c + 3], acc.w); atomicAdd(&ssq[c + 3], acc.w * acc.w);
    }
    __syncthreads();
    if (tid < 128) {
        atomicAdd(&bsum[tid], ssum[tid]);
        atomicAdd(&bsumsq[tid], ssq[tid]);
    }
}

// ---------------- BN finalize ----------------
__global__ void k_bn_fin(const float* __restrict__ gamma, const float* __restrict__ beta,
                         const float* __restrict__ sum, const float* __restrict__ sumsq,
                         float* __restrict__ scale, float* __restrict__ shift, int n) {
    int c = threadIdx.x;
    if (c >= H) return;
    float inv_n = 1.0f / (float)n;
    float mean = sum[c] * inv_n;
    float var = fmaxf(sumsq[c] * inv_n - mean * mean, 0.0f);
    float inv = rsqrtf(var + EPS);
    float sc = gamma[c] * inv;
    scale[c] = sc;
    shift[c] = beta[c] - mean * sc;
}

// ---------------- head ----------------
__global__ __launch_bounds__(256)
void k_head(const float* __restrict__ agg, const float* __restrict__ fcW,
            const float* __restrict__ fcb, const float* __restrict__ scale,
            const float* __restrict__ shift, float* __restrict__ lsm,
            float* __restrict__ logits, int n) {
    __shared__ float Wf[128 * 40];
    __shared__ float fb[40];
    __shared__ float hs[32][129];
    __shared__ float lg[32][40];
    __shared__ float nlse[32];

    int tid = threadIdx.x;
    for (int i = tid; i < 128 * 40; i += 256) Wf[i] = fcW[i];
    if (tid < 40) fb[tid] = fcb[tid];

    int node0 = blockIdx.x * 32;
    for (int i = tid; i < 32 * 128; i += 256) {
        int r = i >> 7, c = i & 127;
        int gn = node0 + r;
        float v = 0.0f;
        if (gn < n) {
            v = agg[(size_t)gn * 128 + c];
            v = fmaxf(v * scale[c] + shift[c], 0.0f);
        }
        hs[r][c] = v;
    }
    __syncthreads();

    int nd = tid >> 3;
    int cg = (tid & 7) * 5;
    float acc[5] = {0, 0, 0, 0, 0};
    for (int k = 0; k < 128; k++) {
        float h = hs[nd][k];
#pragma unroll
        for (int j = 0; j < 5; j++) acc[j] += h * Wf[k * 40 + cg + j];
    }
#pragma unroll
    for (int j = 0; j < 5; j++) lg[nd][cg + j] = fmaxf(acc[j] + fb[cg + j], 0.0f);
    __syncthreads();

    if (tid < 32) {
        float m = -1e30f;
        for (int c = 0; c < 40; c++) m = fmaxf(m, lg[tid][c]);
        float s = 0.0f;
        for (int c = 0; c < 40; c++) s += expf(lg[tid][c] - m);
        nlse[tid] = m + logf(s);
    }
    __syncthreads();

    for (int i = tid; i < 32 * 40; i += 256) {
        int r = i / 40, c = i - r * 40;
        int gn = node0 + r;
        if (gn < n) {
            float l = lg[r][c];
            logits[(size_t)gn * 40 + c] = l;
            lsm[(size_t)gn * 40 + c] = l - nlse[r];
        }
    }
}

// ---------------- host ----------------
extern "C" void kernel_launch(void* const* d_in, const int* in_sizes, int n_in,
                              void* d_out, int out_size) {
    const float* x   = (const float*)d_in[0];
    const int*   ei  = (const int*)d_in[1];
    const float* W1  = (const float*)d_in[2];
    const float* b1  = (const float*)d_in[3];
    const float* W2  = (const float*)d_in[4];
    const float* b2  = (const float*)d_in[5];
    const float* W3  = (const float*)d_in[6];
    const float* b3  = (const float*)d_in[7];
    const float* g1  = (const float*)d_in[8];
    const float* be1 = (const float*)d_in[9];
    const float* g2  = (const float*)d_in[10];
    const float* be2 = (const float*)d_in[11];
    const float* g3  = (const float*)d_in[12];
    const float* be3 = (const float*)d_in[13];
    const float* fcW = (const float*)d_in[14];
    const float* fcb = (const float*)d_in[15];

    int n = in_sizes[0] / H;
    int e = in_sizes[1] / 2;
    const int* src = ei;
    const int* dst = ei + e;

    float *agg, *dis, *cwp, *sum, *sumsq, *scale, *shift, *lscr;
    __half* hw;
    __nv_bfloat16 *wth, *wtl;
    int *cnt, *rowptr, *cursor, *csrc, *bsum, *boff;
    cudaGetSymbolAddress((void**)&hw, g_hw);
    cudaGetSymbolAddress((void**)&agg, g_agg);
    cudaGetSymbolAddress((void**)&dis, g_dis);
    cudaGetSymbolAddress((void**)&cnt, g_cnt);
    cudaGetSymbolAddress((void**)&rowptr, g_rowptr);
    cudaGetSymbolAddress((void**)&cursor, g_cursor);
    cudaGetSymbolAddress((void**)&csrc, g_csrc);
    cudaGetSymbolAddress((void**)&cwp, g_cw);
    cudaGetSymbolAddress((void**)&bsum, g_bsum);
    cudaGetSymbolAddress((void**)&boff, g_boff);
    cudaGetSymbolAddress((void**)&sum, g_sum);
    cudaGetSymbolAddress((void**)&sumsq, g_sumsq);
    cudaGetSymbolAddress((void**)&scale, g_scale);
    cudaGetSymbolAddress((void**)&shift, g_shift);
    cudaGetSymbolAddress((void**)&wth, g_wthi);
    cudaGetSymbolAddress((void**)&wtl, g_wtlo);
    cudaGetSymbolAddress((void**)&lscr, g_logits_scratch);

    float* lsm = (float*)d_out;
    float* logits = (out_size >= 2 * n * CC) ? (lsm + (size_t)n * CC) : lscr;

    int nb = (n + 255) / 256;
    int ebks = (e + 255) / 256;
    int gemm_blocks = (n + 127) / 128;
    int agg_blocks = (n + 7) / 8;
    int scan_blocks = (n + 1023) / 1024;
    int ws_blocks = (H * H + 255) / 256;

    // ---- CSR build ----
    k_zero_cnt<<<nb, 256>>>(cnt, n);
    k_count<<<ebks, 256>>>(dst, cnt, e);
    k_scan_blk<<<scan_blocks, 1024>>>(cnt, rowptr, bsum, dis, n);
    k_scan_top<<<1, 32>>>(bsum, boff, scan_blocks);
    k_scan_add<<<(n + 1023) / 1024, 1024>>>(rowptr, cursor, boff, n, e);
    k_fill<<<ebks, 256>>>(src, dst, dis, cursor, csrc, cwp, e);

    // ---- layer 1 ----
    k_wsplit<<<ws_blocks, 256>>>(W1, wth, wtl, sum, sumsq);
    k_gemm_mma<<<gemm_blocks, 256>>>(x, (const unsigned*)wth, (const unsigned*)wtl,
                                     nullptr, nullptr, hw, n);
    k_aggregate<<<agg_blocks, 256>>>(hw, rowptr, csrc, cwp, b1, dis, agg, sum, sumsq, n);
    k_bn_fin<<<1, 128>>>(g1, be1, sum, sumsq, scale, shift, n);

    // ---- layer 2 ----
    k_wsplit<<<ws_blocks, 256>>>(W2, wth, wtl, sum, sumsq);
    k_gemm_mma<<<gemm_blocks, 256>>>(agg, (const unsigned*)wth, (const unsigned*)wtl,
                                     scale, shift, hw, n);
    k_aggregate<<<agg_blocks, 256>>>(hw, rowptr, csrc, cwp, b2, dis, agg, sum, sumsq, n);
    k_bn_fin<<<1, 128>>>(g2, be2, sum, sumsq, scale, shift, n);

    // ---- layer 3 ----
    k_wsplit<<<ws_blocks, 256>>>(W3, wth, wtl, sum, sumsq);
    k_gemm_mma<<<gemm_blocks, 256>>>(agg, (const unsigned*)wth, (const unsigned*)wtl,
                                     scale, shift, hw, n);
    k_aggregate<<<agg_blocks, 256>>>(hw, rowptr, csrc, cwp, b3, dis, agg, sum, sumsq, n);
    k_bn_fin<<<1, 128>>>(g3, be3, sum, sumsq, scale, shift, n);

    // ---- head ----
    k_head<<<(n + 31) / 32, 256>>>(agg, fcW, fcb, scale, shift, lsm, logits, n);
}

// round 7
// speedup vs baseline: 1.2227x; 1.2227x over previous
#include <cuda_runtime.h>
#include <cuda_fp16.h>
#include <cuda_bf16.h>
#include <math.h>

#define NN 50000
#define MAXE 1600000
#define H 128
#define CC 40
#define EPS 1e-5f

// ---------------- static device scratch ----------------
__device__ __half g_hw[NN * H];      // GEMM output pre-scaled by dis[row], fp16
__device__ float g_agg[NN * H];      // aggregation output (fp32)
__device__ float g_dis[NN];
__device__ int   g_cnt[NN];
__device__ int   g_rowptr[NN + 1];
__device__ int   g_cursor[NN];
__device__ int   g_csrc[MAXE];
__device__ int   g_bsum[128];
__device__ float g_sum[H];
__device__ float g_sumsq[H];
__device__ float g_scale[H];
__device__ float g_shift[H];
__device__ __nv_bfloat16 g_wthi[H * H];
__device__ __nv_bfloat16 g_wtlo[H * H];
__device__ float g_logits_scratch[NN * CC];

// ---------------- CSR build ----------------
__global__ void k_zero_cnt(int* __restrict__ cnt, int n) {
    int i = blockIdx.x * blockDim.x + threadIdx.x;
    if (i < n) cnt[i] = 0;
}

__global__ void k_count(const int* __restrict__ dst, int* __restrict__ cnt, int e) {
    int i = blockIdx.x * blockDim.x + threadIdx.x;
    if (i < e) atomicAdd(&cnt[dst[i]], 1);
}

// scan pass 1 + dis computation fused
__global__ __launch_bounds__(1024)
void k_scan_blk(const int* __restrict__ cnt, int* __restrict__ rowptr,
                int* __restrict__ bsum, float* __restrict__ dis, int n) {
    __shared__ int warpsums[32];
    int tid = threadIdx.x;
    int lane = tid & 31, wid = tid >> 5;
    int i = blockIdx.x * 1024 + tid;
    int v = (i < n) ? cnt[i] : 0;
    if (i < n) dis[i] = rsqrtf((float)(v + 1));
    int x = v;
#pragma unroll
    for (int o = 1; o < 32; o <<= 1) {
        int t = __shfl_up_sync(0xffffffffu, x, o);
        if (lane >= o) x += t;
    }
    if (lane == 31) warpsums[wid] = x;
    __syncthreads();
    if (wid == 0) {
        int w = warpsums[lane];
#pragma unroll
        for (int o = 1; o < 32; o <<= 1) {
            int t = __shfl_up_sync(0xffffffffu, w, o);
            if (lane >= o) w += t;
        }
        warpsums[lane] = w;
    }
    __syncthreads();
    int excl = x - v + (wid > 0 ? warpsums[wid - 1] : 0);
    if (i < n) rowptr[i] = excl;
    if (tid == 1023) bsum[blockIdx.x] = excl + v;
}

// pass 2: add block-prefix (computed locally from bsum), init cursor
__global__ __launch_bounds__(1024)
void k_scan_add(int* __restrict__ rowptr, int* __restrict__ cursor,
                const int* __restrict__ bsum, int n, int e) {
    __shared__ int s_off;
    if (threadIdx.x == 0) {
        int run = 0;
        int nb = (int)blockIdx.x;
        for (int b = 0; b < nb; b++) run += bsum[b];
        s_off = run;
    }
    __syncthreads();
    int i = blockIdx.x * 1024 + threadIdx.x;
    if (i < n) {
        int v = rowptr[i] + s_off;
        rowptr[i] = v;
        cursor[i] = v;
    }
    if (i == 0) rowptr[n] = e;
}

__global__ void k_fill(const int* __restrict__ src, const int* __restrict__ dst,
                       int* __restrict__ cursor, int* __restrict__ csrc, int e) {
    int i = blockIdx.x * blockDim.x + threadIdx.x;
    if (i >= e) return;
    int s = src[i], d = dst[i];
    int pos = atomicAdd(&cursor[d], 1);
    csrc[pos] = s;
}

// ---------------- W split + BN-stat zeroing (fused) ----------------
__global__ void k_wsplit(const float* __restrict__ W, __nv_bfloat16* __restrict__ wth,
                         __nv_bfloat16* __restrict__ wtl,
                         float* __restrict__ sum, float* __restrict__ sumsq) {
    int i = blockIdx.x * blockDim.x + threadIdx.x;
    if (blockIdx.x == 0 && threadIdx.x < H) { sum[threadIdx.x] = 0.0f; sumsq[threadIdx.x] = 0.0f; }
    if (i >= H * H) return;
    int k = i >> 7, nn = i & 127;
    float v = W[i];
    __nv_bfloat16 h = __float2bfloat16(v);
    float rem = v - __bfloat162float(h);
    wth[nn * H + k] = h;
    wtl[nn * H + k] = __float2bfloat16(rem);
}

// ---------------- GEMM via bf16 split MMA; epilogue scales row by dis[row] ----------------
__device__ __forceinline__ void mma16816(float* c, const unsigned* a, const unsigned* b) {
    asm volatile(
        "mma.sync.aligned.m16n8k16.row.col.f32.bf16.bf16.f32 "
        "{%0,%1,%2,%3}, {%4,%5,%6,%7}, {%8,%9}, {%0,%1,%2,%3};"
        : "+f"(c[0]), "+f"(c[1]), "+f"(c[2]), "+f"(c[3])
        : "r"(a[0]), "r"(a[1]), "r"(a[2]), "r"(a[3]), "r"(b[0]), "r"(b[1]));
}

#define APITCH 40

__global__ __launch_bounds__(256, 2)
void k_gemm_mma(const float* __restrict__ A,
                const unsigned* __restrict__ wth,
                const unsigned* __restrict__ wtl,
                const float* __restrict__ scale, const float* __restrict__ shift,
                const float* __restrict__ dis,
                __half* __restrict__ Cout, int n) {
    __shared__ __nv_bfloat16 As_hi[128 * APITCH];
    __shared__ __nv_bfloat16 As_lo[128 * APITCH];
    __shared__ __nv_bfloat16 Ws_hi[128 * APITCH];
    __shared__ __nv_bfloat16 Ws_lo[128 * APITCH];

    int tid = threadIdx.x;
    int w = tid >> 5, lane = tid & 31;
    int wm = w >> 2, wn = w & 3;
    int g = lane >> 2, tig = lane & 3;
    int row0blk = blockIdx.x * 128;

    float acc[4][4][4];
#pragma unroll
    for (int a = 0; a < 4; a++)
#pragma unroll
        for (int b = 0; b < 4; b++)
#pragma unroll
            for (int c = 0; c < 4; c++) acc[a][b][c] = 0.0f;

    for (int k0 = 0; k0 < 128; k0 += 32) {
        for (int i = tid; i < 128 * 32; i += 256) {
            int r = i >> 5, c = i & 31;
            int gr = row0blk + r;
            float v = 0.0f;
            if (gr < n) {
                v = A[(size_t)gr * 128 + k0 + c];
                if (scale) v = fmaxf(v * scale[k0 + c] + shift[k0 + c], 0.0f);
            }
            __nv_bfloat16 h = __float2bfloat16(v);
            As_hi[r * APITCH + c] = h;
            As_lo[r * APITCH + c] = __float2bfloat16(v - __bfloat162float(h));
        }
        for (int i = tid; i < 2048; i += 256) {
            int nn = i >> 4, kk = i & 15;
            ((unsigned*)&Ws_hi[nn * APITCH])[kk] = wth[nn * 64 + (k0 >> 1) + kk];
            ((unsigned*)&Ws_lo[nn * APITCH])[kk] = wtl[nn * 64 + (k0 >> 1) + kk];
        }
        __syncthreads();

#pragma unroll
        for (int ks = 0; ks < 2; ks++) {
            int ca = ks * 16 + 2 * tig;
            unsigned ah[4][4], al[4][4];
#pragma unroll
            for (int mf = 0; mf < 4; mf++) {
                int r0 = (wm * 64 + mf * 16 + g) * APITCH;
                int r1 = r0 + 8 * APITCH;
                ah[mf][0] = *(const unsigned*)&As_hi[r0 + ca];
                ah[mf][1] = *(const unsigned*)&As_hi[r1 + ca];
                ah[mf][2] = *(const unsigned*)&As_hi[r0 + ca + 8];
                ah[mf][3] = *(const unsigned*)&As_hi[r1 + ca + 8];
                al[mf][0] = *(const unsigned*)&As_lo[r0 + ca];
                al[mf][1] = *(const unsigned*)&As_lo[r1 + ca];
                al[mf][2] = *(const unsigned*)&As_lo[r0 + ca + 8];
                al[mf][3] = *(const unsigned*)&As_lo[r1 + ca + 8];
            }
#pragma unroll
            for (int nf = 0; nf < 4; nf++) {
                int nb = (wn * 32 + nf * 8 + g) * APITCH;
                unsigned bh[2], bl[2];
                bh[0] = *(const unsigned*)&Ws_hi[nb + ca];
                bh[1] = *(const unsigned*)&Ws_hi[nb + ca + 8];
                bl[0] = *(const unsigned*)&Ws_lo[nb + ca];
                bl[1] = *(const unsigned*)&Ws_lo[nb + ca + 8];
#pragma unroll
                for (int mf = 0; mf < 4; mf++) {
                    mma16816(acc[mf][nf], ah[mf], bh);
                    mma16816(acc[mf][nf], ah[mf], bl);
                    mma16816(acc[mf][nf], al[mf], bh);
                }
            }
        }
        __syncthreads();
    }

#pragma unroll
    for (int mf = 0; mf < 4; mf++) {
        int gr0 = row0blk + wm * 64 + mf * 16 + g;
        int gr1 = gr0 + 8;
        float ds0 = (gr0 < n) ? dis[gr0] : 0.0f;
        float ds1 = (gr1 < n) ? dis[gr1] : 0.0f;
#pragma unroll
        for (int nf = 0; nf < 4; nf++) {
            int col = wn * 32 + nf * 8 + 2 * tig;
            if (gr0 < n) {
                __half2 h = __floats2half2_rn(acc[mf][nf][0] * ds0, acc[mf][nf][1] * ds0);
                *(unsigned*)&Cout[(size_t)gr0 * 128 + col] = *(unsigned*)&h;
            }
            if (gr1 < n) {
                __half2 h = __floats2half2_rn(acc[mf][nf][2] * ds1, acc[mf][nf][3] * ds1);
                *(unsigned*)&Cout[(size_t)gr1 * 128 + col] = *(unsigned*)&h;
            }
        }
    }
}

// ---------------- pull aggregation: unweighted row sum of pre-scaled rows ----------------
__device__ __forceinline__ void acc_row(float4& acc, const uint2& a) {
    float2 p = __half22float2(*(__half2*)&a.x);
    float2 q = __half22float2(*(__half2*)&a.y);
    acc.x += p.x; acc.y += p.y; acc.z += q.x; acc.w += q.y;
}

__global__ __launch_bounds__(256)
void k_aggregate(const __half* __restrict__ hw, const int* __restrict__ rowptr,
                 const int* __restrict__ csrc,
                 const float* __restrict__ bias, const float* __restrict__ dis,
                 float* __restrict__ agg, float* __restrict__ bsum,
                 float* __restrict__ bsumsq, int n) {
    __shared__ float ssum[128];
    __shared__ float ssq[128];
    int tid = threadIdx.x;
    if (tid < 128) { ssum[tid] = 0.0f; ssq[tid] = 0.0f; }
    __syncthreads();

    int warp = tid >> 5, lane = tid & 31;
    int node = blockIdx.x * 8 + warp;
    if (node < n) {
        const uint2* hw2 = (const uint2*)hw;
        float dd = dis[node];
        float4 b = ((const float4*)bias)[lane];

        // self term: hw is pre-scaled by dis[node]
        uint2 u0 = __ldg(&hw2[(size_t)node * 32 + lane]);
        float2 f0 = __half22float2(*(__half2*)&u0.x);
        float2 f1 = __half22float2(*(__half2*)&u0.y);
        float4 acc = make_float4(f0.x, f0.y, f1.x, f1.y);

        int j = rowptr[node];
        int end = rowptr[node + 1];
        for (; j + 3 < end; j += 4) {
            int i0 = __ldg(&csrc[j]);
            int i1 = __ldg(&csrc[j + 1]);
            int i2 = __ldg(&csrc[j + 2]);
            int i3 = __ldg(&csrc[j + 3]);
            uint2 a0 = __ldg(&hw2[(size_t)i0 * 32 + lane]);
            uint2 a1 = __ldg(&hw2[(size_t)i1 * 32 + lane]);
            uint2 a2 = __ldg(&hw2[(size_t)i2 * 32 + lane]);
            uint2 a3 = __ldg(&hw2[(size_t)i3 * 32 + lane]);
            acc_row(acc, a0);
            acc_row(acc, a1);
            acc_row(acc, a2);
            acc_row(acc, a3);
        }
        for (; j < end; j++) {
            int i0 = __ldg(&csrc[j]);
            uint2 a0 = __ldg(&hw2[(size_t)i0 * 32 + lane]);
            acc_row(acc, a0);
        }

        // final: agg = bias + dis[node] * acc
        float4 outv;
        outv.x = b.x + dd * acc.x;
        outv.y = b.y + dd * acc.y;
        outv.z = b.z + dd * acc.z;
        outv.w = b.w + dd * acc.w;
        ((float4*)agg)[(size_t)node * 32 + lane] = outv;

        int c = lane * 4;
        atomicAdd(&ssum[c + 0], outv.x); atomicAdd(&ssq[c + 0], outv.x * outv.x);
        atomicAdd(&ssum[c + 1], outv.y); atomicAdd(&ssq[c + 1], outv.y * outv.y);
        atomicAdd(&ssum[c + 2], outv.z); atomicAdd(&ssq[c + 2], outv.z * outv.z);
        atomicAdd(&ssum[c + 3], outv.w); atomicAdd(&ssq[c + 3], outv.w * outv.w);
    }
    __syncthreads();
    if (tid < 128) {
        atomicAdd(&bsum[tid], ssum[tid]);
        atomicAdd(&bsumsq[tid], ssq[tid]);
    }
}

// ---------------- BN finalize ----------------
__global__ void k_bn_fin(const float* __restrict__ gamma, const float* __restrict__ beta,
                         const float* __restrict__ sum, const float* __restrict__ sumsq,
                         float* __restrict__ scale, float* __restrict__ shift, int n) {
    int c = threadIdx.x;
    if (c >= H) return;
    float inv_n = 1.0f / (float)n;
    float mean = sum[c] * inv_n;
    float var = fmaxf(sumsq[c] * inv_n - mean * mean, 0.0f);
    float inv = rsqrtf(var + EPS);
    float sc = gamma[c] * inv;
    scale[c] = sc;
    shift[c] = beta[c] - mean * sc;
}

// ---------------- head ----------------
__global__ __launch_bounds__(256)
void k_head(const float* __restrict__ agg, const float* __restrict__ fcW,
            const float* __restrict__ fcb, const float* __restrict__ scale,
            const float* __restrict__ shift, float* __restrict__ lsm,
            float* __restrict__ logits, int n) {
    __shared__ float Wf[128 * 40];
    __shared__ float fb[40];
    __shared__ float hs[32][129];
    __shared__ float lg[32][40];
    __shared__ float nlse[32];

    int tid = threadIdx.x;
    for (int i = tid; i < 128 * 40; i += 256) Wf[i] = fcW[i];
    if (tid < 40) fb[tid] = fcb[tid];

    int node0 = blockIdx.x * 32;
    for (int i = tid; i < 32 * 128; i += 256) {
        int r = i >> 7, c = i & 127;
        int gn = node0 + r;
        float v = 0.0f;
        if (gn < n) {
            v = agg[(size_t)gn * 128 + c];
            v = fmaxf(v * scale[c] + shift[c], 0.0f);
        }
        hs[r][c] = v;
    }
    __syncthreads();

    int nd = tid >> 3;
    int cg = (tid & 7) * 5;
    float acc[5] = {0, 0, 0, 0, 0};
    for (int k = 0; k < 128; k++) {
        float h = hs[nd][k];
#pragma unroll
        for (int j = 0; j < 5; j++) acc[j] += h * Wf[k * 40 + cg + j];
    }
#pragma unroll
    for (int j = 0; j < 5; j++) lg[nd][cg + j] = fmaxf(acc[j] + fb[cg + j], 0.0f);
    __syncthreads();

    if (tid < 32) {
        float m = -1e30f;
        for (int c = 0; c < 40; c++) m = fmaxf(m, lg[tid][c]);
        float s = 0.0f;
        for (int c = 0; c < 40; c++) s += expf(lg[tid][c] - m);
        nlse[tid] = m + logf(s);
    }
    __syncthreads();

    for (int i = tid; i < 32 * 40; i += 256) {
        int r = i / 40, c = i - r * 40;
        int gn = node0 + r;
        if (gn < n) {
            float l = lg[r][c];
            logits[(size_t)gn * 40 + c] = l;
            lsm[(size_t)gn * 40 + c] = l - nlse[r];
        }
    }
}

// ---------------- host ----------------
extern "C" void kernel_launch(void* const* d_in, const int* in_sizes, int n_in,
                              void* d_out, int out_size) {
    const float* x   = (const float*)d_in[0];
    const int*   ei  = (const int*)d_in[1];
    const float* W1  = (const float*)d_in[2];
    const float* b1  = (const float*)d_in[3];
    const float* W2  = (const float*)d_in[4];
    const float* b2  = (const float*)d_in[5];
    const float* W3  = (const float*)d_in[6];
    const float* b3  = (const float*)d_in[7];
    const float* g1  = (const float*)d_in[8];
    const float* be1 = (const float*)d_in[9];
    const float* g2  = (const float*)d_in[10];
    const float* be2 = (const float*)d_in[11];
    const float* g3  = (const float*)d_in[12];
    const float* be3 = (const float*)d_in[13];
    const float* fcW = (const float*)d_in[14];
    const float* fcb = (const float*)d_in[15];

    int n = in_sizes[0] / H;
    int e = in_sizes[1] / 2;
    const int* src = ei;
    const int* dst = ei + e;

    float *agg, *dis, *sum, *sumsq, *scale, *shift, *lscr;
    __half* hw;
    __nv_bfloat16 *wth, *wtl;
    int *cnt, *rowptr, *cursor, *csrc, *bsum;
    cudaGetSymbolAddress((void**)&hw, g_hw);
    cudaGetSymbolAddress((void**)&agg, g_agg);
    cudaGetSymbolAddress((void**)&dis, g_dis);
    cudaGetSymbolAddress((void**)&cnt, g_cnt);
    cudaGetSymbolAddress((void**)&rowptr, g_rowptr);
    cudaGetSymbolAddress((void**)&cursor, g_cursor);
    cudaGetSymbolAddress((void**)&csrc, g_csrc);
    cudaGetSymbolAddress((void**)&bsum, g_bsum);
    cudaGetSymbolAddress((void**)&sum, g_sum);
    cudaGetSymbolAddress((void**)&sumsq, g_sumsq);
    cudaGetSymbolAddress((void**)&scale, g_scale);
    cudaGetSymbolAddress((void**)&shift, g_shift);
    cudaGetSymbolAddress((void**)&wth, g_wthi);
    cudaGetSymbolAddress((void**)&wtl, g_wtlo);
    cudaGetSymbolAddress((void**)&lscr, g_logits_scratch);

    float* lsm = (float*)d_out;
    float* logits = (out_size >= 2 * n * CC) ? (lsm + (size_t)n * CC) : lscr;

    int nb = (n + 255) / 256;
    int ebks = (e + 255) / 256;
    int gemm_blocks = (n + 127) / 128;
    int agg_blocks = (n + 7) / 8;
    int scan_blocks = (n + 1023) / 1024;
    int ws_blocks = (H * H + 255) / 256;

    // ---- CSR build ----
    k_zero_cnt<<<nb, 256>>>(cnt, n);
    k_count<<<ebks, 256>>>(dst, cnt, e);
    k_scan_blk<<<scan_blocks, 1024>>>(cnt, rowptr, bsum, dis, n);
    k_scan_add<<<scan_blocks, 1024>>>(rowptr, cursor, bsum, n, e);
    k_fill<<<ebks, 256>>>(src, dst, cursor, csrc, e);

    // ---- layer 1 ----
    k_wsplit<<<ws_blocks, 256>>>(W1, wth, wtl, sum, sumsq);
    k_gemm_mma<<<gemm_blocks, 256>>>(x, (const unsigned*)wth, (const unsigned*)wtl,
                                     nullptr, nullptr, dis, hw, n);
    k_aggregate<<<agg_blocks, 256>>>(hw, rowptr, csrc, b1, dis, agg, sum, sumsq, n);
    k_bn_fin<<<1, 128>>>(g1, be1, sum, sumsq, scale, shift, n);

    // ---- layer 2 ----
    k_wsplit<<<ws_blocks, 256>>>(W2, wth, wtl, sum, sumsq);
    k_gemm_mma<<<gemm_blocks, 256>>>(agg, (const unsigned*)wth, (const unsigned*)wtl,
                                     scale, shift, dis, hw, n);
    k_aggregate<<<agg_blocks, 256>>>(hw, rowptr, csrc, b2, dis, agg, sum, sumsq, n);
    k_bn_fin<<<1, 128>>>(g2, be2, sum, sumsq, scale, shift, n);

    // ---- layer 3 ----
    k_wsplit<<<ws_blocks, 256>>>(W3, wth, wtl, sum, sumsq);
    k_gemm_mma<<<gemm_blocks, 256>>>(agg, (const unsigned*)wth, (const unsigned*)wtl,
                                     scale, shift, dis, hw, n);
    k_aggregate<<<agg_blocks, 256>>>(hw, rowptr, csrc, b3, dis, agg, sum, sumsq, n);
    k_bn_fin<<<1, 128>>>(g3, be3, sum, sumsq, scale, shift, n);

    // ---- head ----
    k_head<<<(n + 31) / 32, 256>>>(agg, fcW, fcb, scale, shift, lsm, logits, n);
}